// round 4
// baseline (speedup 1.0000x reference)
#include <cuda_runtime.h>
#include <cuda_bf16.h>
#include <math.h>
#include <stdint.h>

// Problem constants
#define TT 2048
#define BB 8
#define DD 1024
#define NS 1024
#define NBLK 128
#define MM (TT*BB)        // 16384 projection rows
#define KP 3072           // K' = 3*D  (bf16x3 split concatenated along K)
#define NP 3072           // N' = 3*N_STATE (k,v,q concatenated along N)

// Scratch (device globals: no cudaMalloc allowed)
__device__ __nv_bfloat16 g_A[(size_t)MM * KP];   // [Ah | Ah | Al]
__device__ __nv_bfloat16 g_B[(size_t)NP * KP];   // rows: Wk,Wv,Wq; cols: [Bh | Bl | Bh]
__device__ float         g_P[(size_t)MM * NP];   // cols 0-1023=k, 1024-2047=v, 2048-3071=q

// ---------------------------------------------------------------------------
// Helpers
// ---------------------------------------------------------------------------
static __device__ __forceinline__ uint32_t smem_u32(const void* p) {
    uint32_t a;
    asm("{ .reg .u64 t; cvta.to.shared.u64 t, %1; cvt.u32.u64 %0, t; }" : "=r"(a) : "l"(p));
    return a;
}
#define SWZ(off) ((off) ^ (((off) >> 3) & 0x70))

#define CP_ASYNC16(saddr, gaddr) \
    asm volatile("cp.async.cg.shared.global [%0], [%1], 16;" :: "r"(saddr), "l"(gaddr))
#define CP_COMMIT() asm volatile("cp.async.commit_group;" ::: "memory")
#define CP_WAIT(n)  asm volatile("cp.async.wait_group %0;" :: "n"(n) : "memory")

#define LDSM_X4(r0, r1, r2, r3, addr) \
    asm volatile("ldmatrix.sync.aligned.m8n8.x4.shared.b16 {%0,%1,%2,%3}, [%4];" \
                 : "=r"(r0), "=r"(r1), "=r"(r2), "=r"(r3) : "r"(addr))

static __device__ __forceinline__ void mma16816(float* d, const uint32_t* a,
                                                const uint32_t* b) {
    asm volatile(
        "mma.sync.aligned.m16n8k16.row.col.f32.bf16.bf16.f32 "
        "{%0,%1,%2,%3}, {%4,%5,%6,%7}, {%8,%9}, {%0,%1,%2,%3};"
        : "+f"(d[0]), "+f"(d[1]), "+f"(d[2]), "+f"(d[3])
        : "r"(a[0]), "r"(a[1]), "r"(a[2]), "r"(a[3]), "r"(b[0]), "r"(b[1]));
}

// Fast-math primitives (MUFU)
static __device__ __forceinline__ float f_ex2(float x)  { float r; asm("ex2.approx.f32 %0, %1;"  : "=f"(r) : "f"(x)); return r; }
static __device__ __forceinline__ float f_rcp(float x)  { float r; asm("rcp.approx.f32 %0, %1;"  : "=f"(r) : "f"(x)); return r; }
static __device__ __forceinline__ float f_sqrt(float x) { float r; asm("sqrt.approx.f32 %0, %1;" : "=f"(r) : "f"(x)); return r; }
static __device__ __forceinline__ float f_tanh(float x) {
    // tanh(x) = 1 - 2/(e^{2x}+1);  e^{2x} = 2^{x * 2/ln2}
    float u = f_ex2(x * 2.8853900817779268f);
    return fmaf(-2.0f, f_rcp(u + 1.0f), 1.0f);
}
static __device__ __forceinline__ float dot8(const float* a, const float* b) {
    float p0 = a[0]*b[0], p1 = a[1]*b[1], p2 = a[2]*b[2], p3 = a[3]*b[3];
    float p4 = a[4]*b[4], p5 = a[5]*b[5], p6 = a[6]*b[6], p7 = a[7]*b[7];
    return ((p0+p1)+(p2+p3)) + ((p4+p5)+(p6+p7));
}

// ---------------------------------------------------------------------------
// Conversion: fp32 -> bf16 hi/lo split, concatenated along K
// ---------------------------------------------------------------------------
static __device__ __forceinline__ uint2 pack4(const float* f, bool lo_part) {
    unsigned short h[4];
#pragma unroll
    for (int j = 0; j < 4; j++) {
        __nv_bfloat16 hi = __float2bfloat16(f[j]);
        if (!lo_part) h[j] = __bfloat16_as_ushort(hi);
        else          h[j] = __bfloat16_as_ushort(__float2bfloat16(f[j] - __bfloat162float(hi)));
    }
    uint2 r;
    r.x = (uint32_t)h[0] | ((uint32_t)h[1] << 16);
    r.y = (uint32_t)h[2] | ((uint32_t)h[3] << 16);
    return r;
}

__global__ void __launch_bounds__(256)
convert_x_kernel(const float* __restrict__ X) {
    size_t i = (size_t)blockIdx.x * 256 + threadIdx.x;   // unit = 4 floats
    size_t e = i * 4;
    size_t m = e / DD;
    int    c = (int)(e % DD);
    float4 a = *(const float4*)(X + e);
    float f[4] = {a.x, a.y, a.z, a.w};
    uint2 hp = pack4(f, false);
    uint2 lp = pack4(f, true);
    __nv_bfloat16* row = g_A + m * KP;
    *(uint2*)(row + c)        = hp;   // segment 0: Ah
    *(uint2*)(row + c + DD)   = hp;   // segment 1: Ah
    *(uint2*)(row + c + 2*DD) = lp;   // segment 2: Al
}

__global__ void __launch_bounds__(256)
convert_w_kernel(const float* __restrict__ Wk, const float* __restrict__ Wv,
                 const float* __restrict__ Wq) {
    size_t i = (size_t)blockIdx.x * 256 + threadIdx.x;
    size_t e = i * 4;
    int    w = (int)(e / ((size_t)NS * DD));
    size_t r = e % ((size_t)NS * DD);
    const float* W = (w == 0) ? Wk : ((w == 1) ? Wv : Wq);
    size_t n = r / DD;
    int    c = (int)(r % DD);
    float4 a = *(const float4*)(W + r);
    float f[4] = {a.x, a.y, a.z, a.w};
    uint2 hp = pack4(f, false);
    uint2 lp = pack4(f, true);
    __nv_bfloat16* row = g_B + ((size_t)w * NS + n) * KP;
    *(uint2*)(row + c)        = hp;   // segment 0: Bh
    *(uint2*)(row + c + DD)   = lp;   // segment 1: Bl
    *(uint2*)(row + c + 2*DD) = hp;   // segment 2: Bh
}

// ---------------------------------------------------------------------------
// bf16 GEMM via mma.sync: g_P[m,n] = sum_k g_A[m,k] * g_B[n,k]
// CTA tile 128x128, BK=64 (SW128 rows), 3-stage cp.async pipeline with ONE
// barrier per chunk and 2 stages in flight during compute.
// ---------------------------------------------------------------------------
#define TM 128
#define TN 128
#define CK 64
#define NCH (KP / CK)     // 48
#define STAGES 3
#define STG_BYTES (2 * TM * CK * 2)       // A tile + B tile = 32768
#define GEMM_SMEM (STAGES * STG_BYTES)    // 98304

__global__ void __launch_bounds__(256, 2)
gemm_kernel() {
    extern __shared__ char smem[];
    const uint32_t sb  = smem_u32(smem);
    const int tid = threadIdx.x;
    const int wid = tid >> 5;
    const int lid = tid & 31;
    const size_t bm = (size_t)blockIdx.y * TM;
    const size_t bn = (size_t)blockIdx.x * TN;

    const int wm = wid & 1;          // 2 M-slabs of 64
    const int wn = wid >> 1;         // 4 N-slabs of 32

    const __nv_bfloat16* Abase = g_A + bm * KP;
    const __nv_bfloat16* Bbase = g_B + bn * KP;

    auto issue_stage = [&](int i) {
        const uint32_t abuf = sb + (i % STAGES) * STG_BYTES;
        const uint32_t bbuf = abuf + TM * CK * 2;
        const __nv_bfloat16* As = Abase + i * CK;
        const __nv_bfloat16* Bs = Bbase + i * CK;
#pragma unroll
        for (int u = 0; u < 4; u++) {
            int unit = tid + u * 256;
            int r = unit >> 3, c = unit & 7;
            uint32_t off = SWZ(r * 128 + c * 16);
            CP_ASYNC16(abuf + off, (const char*)(As + (size_t)r * KP + c * 8));
            CP_ASYNC16(bbuf + off, (const char*)(Bs + (size_t)r * KP + c * 8));
        }
        CP_COMMIT();
    };

    issue_stage(0);
    issue_stage(1);

    float acc[4][4][4];
#pragma unroll
    for (int i = 0; i < 4; i++)
#pragma unroll
        for (int j = 0; j < 4; j++)
#pragma unroll
            for (int r = 0; r < 4; r++) acc[i][j][r] = 0.0f;

    const int lrow  = (lid & 7) + ((lid >> 3) & 1) * 8;
    const int chalf = lid >> 4;

    for (int it = 0; it < NCH; it++) {
        CP_WAIT(1);                 // stage `it` resident (one newer may pend)
        __syncthreads();            // all warps done reading buffer (it-1)%3
        if (it + 2 < NCH) issue_stage(it + 2);   // overwrites (it-1)%3: safe
        else CP_COMMIT();                        // keep group accounting uniform

        const uint32_t abuf = sb + (it % STAGES) * STG_BYTES;
        const uint32_t bbuf = abuf + TM * CK * 2;

#pragma unroll
        for (int s = 0; s < 4; s++) {          // k16 steps within CK=64
            const int ch = 2 * s + chalf;
            uint32_t a[4][4];
#pragma unroll
            for (int mf = 0; mf < 4; mf++) {
                uint32_t addr = abuf + SWZ((wm * 64 + mf * 16 + lrow) * 128 + ch * 16);
                LDSM_X4(a[mf][0], a[mf][1], a[mf][2], a[mf][3], addr);
            }
            uint32_t b[2][4];
#pragma unroll
            for (int nf2 = 0; nf2 < 2; nf2++) {
                uint32_t addr = bbuf + SWZ((wn * 32 + nf2 * 16 + lrow) * 128 + ch * 16);
                LDSM_X4(b[nf2][0], b[nf2][1], b[nf2][2], b[nf2][3], addr);
            }
#pragma unroll
            for (int mf = 0; mf < 4; mf++) {
#pragma unroll
                for (int nf = 0; nf < 4; nf++) {
                    uint32_t bb_[2] = { b[nf >> 1][(nf & 1)], b[nf >> 1][(nf & 1) + 2] };
                    mma16816(acc[mf][nf], a[mf], bb_);
                }
            }
        }
    }

    // Epilogue: direct float2 stores
    const int r0 = lid >> 2;
    const int cp = (lid & 3) * 2;
#pragma unroll
    for (int mf = 0; mf < 4; mf++) {
#pragma unroll
        for (int nf = 0; nf < 4; nf++) {
            float* dst = g_P + (bm + wm * 64 + mf * 16 + r0) * (size_t)NP
                             + bn + wn * 32 + nf * 8 + cp;
            *(float2*)dst = make_float2(acc[mf][nf][0], acc[mf][nf][1]);
            *(float2*)(dst + 8 * NP) = make_float2(acc[mf][nf][2], acc[mf][nf][3]);
        }
    }
}

// ---------------------------------------------------------------------------
// Recurrent delta-rule scan. Critical path through S minimized: k-norm is
// S-independent (computed in the prefetch shadow), dots are trees, tanh is
// ex2+rcp (2 MUFU), output silu is off the S-chain.
// ---------------------------------------------------------------------------
__global__ void __launch_bounds__(64)
scan_kernel(float* __restrict__ out, int write_sf)
{
    const int c    = blockIdx.x * 8 + (threadIdx.x >> 3);  // chain 0..1023
    const int lane = threadIdx.x & 7;
    const int b  = c >> 7;
    const int nb = c & 127;

    const float* kp = g_P + (size_t)b * NP + nb * 8;
    const float* vp = g_P + (size_t)b * NP + NS + nb * 8 + lane;
    const float* qp = g_P + (size_t)b * NP + 2 * NS + nb * 8;
    float*       op = out + (size_t)b * NS + nb * 8 + lane;

    const int pstride = BB * NP;
    const int ostride = BB * NS;

    float S[8];
#pragma unroll
    for (int j = 0; j < 8; j++) S[j] = 0.0f;

    float4 ka = *(const float4*)(kp);
    float4 kb = *(const float4*)(kp + 4);
    float4 qa = *(const float4*)(qp);
    float4 qb = *(const float4*)(qp + 4);
    float  vv = *vp;

    for (int t = 0; t < TT; t++) {
        float kc[8] = { ka.x, ka.y, ka.z, ka.w, kb.x, kb.y, kb.z, kb.w };
        float qc[8] = { qa.x, qa.y, qa.z, qa.w, qb.x, qb.y, qb.z, qb.w };
        float vc = vv;

        if (t + 1 < TT) {
            const float* kn_ = kp + (size_t)(t + 1) * pstride;
            const float* qn_ = qp + (size_t)(t + 1) * pstride;
            ka = *(const float4*)(kn_);
            kb = *(const float4*)(kn_ + 4);
            qa = *(const float4*)(qn_);
            qb = *(const float4*)(qn_ + 4);
            vv = vp[(size_t)(t + 1) * pstride];
        }

        // k_norm (independent of S)
        float ss  = dot8(kc, kc);
        float inv = f_rcp(f_sqrt(ss) + 1e-6f);
#pragma unroll
        for (int j = 0; j < 8; j++) kc[j] *= inv;

        // S-chain: retrieve -> delta -> tanh update
        float r = dot8(S, kc);
        float delta = vc - r;
#pragma unroll
        for (int j = 0; j < 8; j++) S[j] = f_tanh(fmaf(delta, kc[j], S[j]));

        // output (consumes S, not on next step's critical path)
        float sq  = dot8(S, qc);
        float sig = f_rcp(1.0f + f_ex2(sq * -1.4426950408889634f));
        op[(size_t)t * ostride] = sq * sq * sig;
    }

    if (write_sf) {
        float* sf = out + (size_t)MM * NS + (size_t)c * 64 + lane * 8;
#pragma unroll
        for (int j = 0; j < 8; j++) sf[j] = S[j];
    }
}

// ---------------------------------------------------------------------------
extern "C" void kernel_launch(void* const* d_in, const int* in_sizes, int n_in,
                              void* d_out, int out_size)
{
    (void)in_sizes; (void)n_in;
    const float* x  = (const float*)d_in[0];
    const float* wk = (const float*)d_in[1];
    const float* wv = (const float*)d_in[2];
    const float* wq = (const float*)d_in[3];
    float* out = (float*)d_out;

    convert_x_kernel<<<(MM * DD / 4) / 256, 256>>>(x);
    convert_w_kernel<<<(3 * NS * DD / 4) / 256, 256>>>(wk, wv, wq);

    cudaFuncSetAttribute(gemm_kernel, cudaFuncAttributeMaxDynamicSharedMemorySize, GEMM_SMEM);
    dim3 ggrid(NP / TN, MM / TM);   // 24 x 128
    gemm_kernel<<<ggrid, 256, GEMM_SMEM>>>();

    const long long n_out   = (long long)MM * NS;
    const long long n_state = (long long)BB * NBLK * 64;
    int write_sf = ((long long)out_size >= n_out + n_state) ? 1 : 0;
    scan_kernel<<<128, 64>>>(out, write_sf);
}

// round 5
// speedup vs baseline: 1.5102x; 1.5102x over previous
#include <cuda_runtime.h>
#include <cuda_bf16.h>
#include <math.h>
#include <stdint.h>

// Problem constants
#define TT 2048
#define BB 8
#define DD 1024
#define NS 1024
#define NBLK 128
#define MM (TT*BB)        // 16384 projection rows
#define KP 3072           // K' = 3*D  (bf16x3 split concatenated along K)
#define NP 3072           // N' = 3*N_STATE (k,v,q concatenated along N)

// Scratch (device globals: no cudaMalloc allowed)
__device__ __nv_bfloat16 g_A[(size_t)MM * KP];   // [Ah | Ah | Al]
__device__ __nv_bfloat16 g_B[(size_t)NP * KP];   // rows: Wk,Wv,Wq; cols: [Bh | Bl | Bh]
__device__ float         g_P[(size_t)MM * NP];   // cols 0-1023=k, 1024-2047=v, 2048-3071=q

// ---------------------------------------------------------------------------
// Helpers
// ---------------------------------------------------------------------------
static __device__ __forceinline__ uint32_t smem_u32(const void* p) {
    uint32_t a;
    asm("{ .reg .u64 t; cvta.to.shared.u64 t, %1; cvt.u32.u64 %0, t; }" : "=r"(a) : "l"(p));
    return a;
}
#define SWZ(off) ((off) ^ (((off) >> 3) & 0x70))

#define CP_ASYNC16(saddr, gaddr) \
    asm volatile("cp.async.cg.shared.global [%0], [%1], 16;" :: "r"(saddr), "l"(gaddr))
#define CP_ASYNC4(saddr, gaddr) \
    asm volatile("cp.async.ca.shared.global [%0], [%1], 4;" :: "r"(saddr), "l"(gaddr))
#define CP_COMMIT() asm volatile("cp.async.commit_group;" ::: "memory")
#define CP_WAIT(n)  asm volatile("cp.async.wait_group %0;" :: "n"(n) : "memory")

#define LDSM_X4(r0, r1, r2, r3, addr) \
    asm volatile("ldmatrix.sync.aligned.m8n8.x4.shared.b16 {%0,%1,%2,%3}, [%4];" \
                 : "=r"(r0), "=r"(r1), "=r"(r2), "=r"(r3) : "r"(addr))

static __device__ __forceinline__ void mma16816(float* d, const uint32_t* a,
                                                const uint32_t* b) {
    asm volatile(
        "mma.sync.aligned.m16n8k16.row.col.f32.bf16.bf16.f32 "
        "{%0,%1,%2,%3}, {%4,%5,%6,%7}, {%8,%9}, {%0,%1,%2,%3};"
        : "+f"(d[0]), "+f"(d[1]), "+f"(d[2]), "+f"(d[3])
        : "r"(a[0]), "r"(a[1]), "r"(a[2]), "r"(a[3]), "r"(b[0]), "r"(b[1]));
}

// Fast-math primitives (MUFU)
static __device__ __forceinline__ float f_ex2(float x)  { float r; asm("ex2.approx.f32 %0, %1;"  : "=f"(r) : "f"(x)); return r; }
static __device__ __forceinline__ float f_rcp(float x)  { float r; asm("rcp.approx.f32 %0, %1;"  : "=f"(r) : "f"(x)); return r; }
static __device__ __forceinline__ float f_sqrt(float x) { float r; asm("sqrt.approx.f32 %0, %1;" : "=f"(r) : "f"(x)); return r; }
static __device__ __forceinline__ float f_tanh(float x) {
    float u = f_ex2(x * 2.8853900817779268f);
    return fmaf(-2.0f, f_rcp(u + 1.0f), 1.0f);
}
static __device__ __forceinline__ float dot8(const float* a, const float* b) {
    float p0 = a[0]*b[0], p1 = a[1]*b[1], p2 = a[2]*b[2], p3 = a[3]*b[3];
    float p4 = a[4]*b[4], p5 = a[5]*b[5], p6 = a[6]*b[6], p7 = a[7]*b[7];
    return ((p0+p1)+(p2+p3)) + ((p4+p5)+(p6+p7));
}

// ---------------------------------------------------------------------------
// Conversion: fp32 -> bf16 hi/lo split, concatenated along K
// ---------------------------------------------------------------------------
static __device__ __forceinline__ uint2 pack4(const float* f, bool lo_part) {
    unsigned short h[4];
#pragma unroll
    for (int j = 0; j < 4; j++) {
        __nv_bfloat16 hi = __float2bfloat16(f[j]);
        if (!lo_part) h[j] = __bfloat16_as_ushort(hi);
        else          h[j] = __bfloat16_as_ushort(__float2bfloat16(f[j] - __bfloat162float(hi)));
    }
    uint2 r;
    r.x = (uint32_t)h[0] | ((uint32_t)h[1] << 16);
    r.y = (uint32_t)h[2] | ((uint32_t)h[3] << 16);
    return r;
}

__global__ void __launch_bounds__(256)
convert_x_kernel(const float* __restrict__ X) {
    size_t i = (size_t)blockIdx.x * 256 + threadIdx.x;
    size_t e = i * 4;
    size_t m = e / DD;
    int    c = (int)(e % DD);
    float4 a = *(const float4*)(X + e);
    float f[4] = {a.x, a.y, a.z, a.w};
    uint2 hp = pack4(f, false);
    uint2 lp = pack4(f, true);
    __nv_bfloat16* row = g_A + m * KP;
    *(uint2*)(row + c)        = hp;
    *(uint2*)(row + c + DD)   = hp;
    *(uint2*)(row + c + 2*DD) = lp;
}

__global__ void __launch_bounds__(256)
convert_w_kernel(const float* __restrict__ Wk, const float* __restrict__ Wv,
                 const float* __restrict__ Wq) {
    size_t i = (size_t)blockIdx.x * 256 + threadIdx.x;
    size_t e = i * 4;
    int    w = (int)(e / ((size_t)NS * DD));
    size_t r = e % ((size_t)NS * DD);
    const float* W = (w == 0) ? Wk : ((w == 1) ? Wv : Wq);
    size_t n = r / DD;
    int    c = (int)(r % DD);
    float4 a = *(const float4*)(W + r);
    float f[4] = {a.x, a.y, a.z, a.w};
    uint2 hp = pack4(f, false);
    uint2 lp = pack4(f, true);
    __nv_bfloat16* row = g_B + ((size_t)w * NS + n) * KP;
    *(uint2*)(row + c)        = hp;
    *(uint2*)(row + c + DD)   = lp;
    *(uint2*)(row + c + 2*DD) = hp;
}

// ---------------------------------------------------------------------------
// bf16 GEMM via mma.sync (unchanged from round 4)
// ---------------------------------------------------------------------------
#define TM 128
#define TN 128
#define CK 64
#define NCH (KP / CK)     // 48
#define STAGES 3
#define STG_BYTES (2 * TM * CK * 2)
#define GEMM_SMEM (STAGES * STG_BYTES)

__global__ void __launch_bounds__(256, 2)
gemm_kernel() {
    extern __shared__ char smem[];
    const uint32_t sb  = smem_u32(smem);
    const int tid = threadIdx.x;
    const int wid = tid >> 5;
    const int lid = tid & 31;
    const size_t bm = (size_t)blockIdx.y * TM;
    const size_t bn = (size_t)blockIdx.x * TN;

    const int wm = wid & 1;
    const int wn = wid >> 1;

    const __nv_bfloat16* Abase = g_A + bm * KP;
    const __nv_bfloat16* Bbase = g_B + bn * KP;

    auto issue_stage = [&](int i) {
        const uint32_t abuf = sb + (i % STAGES) * STG_BYTES;
        const uint32_t bbuf = abuf + TM * CK * 2;
        const __nv_bfloat16* As = Abase + i * CK;
        const __nv_bfloat16* Bs = Bbase + i * CK;
#pragma unroll
        for (int u = 0; u < 4; u++) {
            int unit = tid + u * 256;
            int r = unit >> 3, c = unit & 7;
            uint32_t off = SWZ(r * 128 + c * 16);
            CP_ASYNC16(abuf + off, (const char*)(As + (size_t)r * KP + c * 8));
            CP_ASYNC16(bbuf + off, (const char*)(Bs + (size_t)r * KP + c * 8));
        }
        CP_COMMIT();
    };

    issue_stage(0);
    issue_stage(1);

    float acc[4][4][4];
#pragma unroll
    for (int i = 0; i < 4; i++)
#pragma unroll
        for (int j = 0; j < 4; j++)
#pragma unroll
            for (int r = 0; r < 4; r++) acc[i][j][r] = 0.0f;

    const int lrow  = (lid & 7) + ((lid >> 3) & 1) * 8;
    const int chalf = lid >> 4;

    for (int it = 0; it < NCH; it++) {
        CP_WAIT(1);
        __syncthreads();
        if (it + 2 < NCH) issue_stage(it + 2);
        else CP_COMMIT();

        const uint32_t abuf = sb + (it % STAGES) * STG_BYTES;
        const uint32_t bbuf = abuf + TM * CK * 2;

#pragma unroll
        for (int s = 0; s < 4; s++) {
            const int ch = 2 * s + chalf;
            uint32_t a[4][4];
#pragma unroll
            for (int mf = 0; mf < 4; mf++) {
                uint32_t addr = abuf + SWZ((wm * 64 + mf * 16 + lrow) * 128 + ch * 16);
                LDSM_X4(a[mf][0], a[mf][1], a[mf][2], a[mf][3], addr);
            }
            uint32_t b[2][4];
#pragma unroll
            for (int nf2 = 0; nf2 < 2; nf2++) {
                uint32_t addr = bbuf + SWZ((wn * 32 + nf2 * 16 + lrow) * 128 + ch * 16);
                LDSM_X4(b[nf2][0], b[nf2][1], b[nf2][2], b[nf2][3], addr);
            }
#pragma unroll
            for (int mf = 0; mf < 4; mf++) {
#pragma unroll
                for (int nf = 0; nf < 4; nf++) {
                    uint32_t bb_[2] = { b[nf >> 1][(nf & 1)], b[nf >> 1][(nf & 1) + 2] };
                    mma16816(acc[mf][nf], a[mf], bb_);
                }
            }
        }
    }

    const int r0 = lid >> 2;
    const int cp = (lid & 3) * 2;
#pragma unroll
    for (int mf = 0; mf < 4; mf++) {
#pragma unroll
        for (int nf = 0; nf < 4; nf++) {
            float* dst = g_P + (bm + wm * 64 + mf * 16 + r0) * (size_t)NP
                             + bn + wn * 32 + nf * 8 + cp;
            *(float2*)dst = make_float2(acc[mf][nf][0], acc[mf][nf][1]);
            *(float2*)(dst + 8 * NP) = make_float2(acc[mf][nf][2], acc[mf][nf][3]);
        }
    }
}

// ---------------------------------------------------------------------------
// Recurrent delta-rule scan with a DEEP cp.async pipeline.
// Each 64-thread block serves 8 chains; per step it needs 3 x 256B contiguous
// slices of g_P (k, v, q). A 16-stage smem ring + per-thread 4B cp.async
// (1 group/step) hides the ~577cy DRAM latency behind 15 steps of compute.
// wait_group<13> guarantees stages t AND t+1 are resident, so next-step regs
// load one step early.
// ---------------------------------------------------------------------------
#define SDEPTH 16
#define STG_F 192          // floats per stage: k[64] v[64] q[64]

__global__ void __launch_bounds__(64)
scan_kernel(float* __restrict__ out, int write_sf)
{
    __shared__ float ring[SDEPTH * STG_F];

    const int tid  = threadIdx.x;
    const int c    = blockIdx.x * 8 + (tid >> 3);   // chain 0..1023
    const int lane = tid & 7;
    const int b    = c >> 7;
    const int nb   = c & 127;

    // block-level source window: 64 consecutive state columns
    const int cBase = blockIdx.x * 8;
    const int col0  = (cBase & 127) * 8;
    const float* src = g_P + (size_t)b * NP + col0;   // + t*BB*NP per step
    const size_t pstep = (size_t)BB * NP;

    const uint32_t rb = smem_u32(ring);
    const int ch8 = (tid >> 3) * 8;

    // per-thread cp.async targets (4B each: k, v, q)
    auto issue = [&](int t) {
        const float* s = src + (size_t)t * pstep;
        uint32_t st = rb + (t % SDEPTH) * (STG_F * 4);
        CP_ASYNC4(st + tid * 4,             (const char*)(s + tid));
        CP_ASYNC4(st + (64 + tid) * 4,      (const char*)(s + NS + tid));
        CP_ASYNC4(st + (128 + tid) * 4,     (const char*)(s + 2 * NS + tid));
        CP_COMMIT();
    };

    float*       op = out + (size_t)b * NS + nb * 8 + lane;
    const int ostride = BB * NS;

    float S[8];
#pragma unroll
    for (int j = 0; j < 8; j++) S[j] = 0.0f;

    // prologue: fill 14 stages
    for (int s = 0; s < 14; s++) issue(s);
    CP_WAIT(13);
    __syncthreads();

    // regs for t=0
    float kc[8], qc[8], vv;
    {
        const float* st = ring;   // stage 0
        float4 k0 = *(const float4*)(st + ch8);
        float4 k1 = *(const float4*)(st + ch8 + 4);
        float4 q0 = *(const float4*)(st + 128 + ch8);
        float4 q1 = *(const float4*)(st + 128 + ch8 + 4);
        kc[0]=k0.x; kc[1]=k0.y; kc[2]=k0.z; kc[3]=k0.w;
        kc[4]=k1.x; kc[5]=k1.y; kc[6]=k1.z; kc[7]=k1.w;
        qc[0]=q0.x; qc[1]=q0.y; qc[2]=q0.z; qc[3]=q0.w;
        qc[4]=q1.x; qc[5]=q1.y; qc[6]=q1.z; qc[7]=q1.w;
        vv = st[64 + ch8 + lane];
    }

    for (int t = 0; t < TT; t++) {
        // ---- compute step t (regs already loaded) ----
        float kn[8];
        float ss  = dot8(kc, kc);
        float inv = f_rcp(f_sqrt(ss) + 1e-6f);
#pragma unroll
        for (int j = 0; j < 8; j++) kn[j] = kc[j] * inv;

        float r = dot8(S, kn);
        float delta = vv - r;
#pragma unroll
        for (int j = 0; j < 8; j++) S[j] = f_tanh(fmaf(delta, kn[j], S[j]));

        float sq  = dot8(S, qc);
        float sig = f_rcp(1.0f + f_ex2(sq * -1.4426950408889634f));
        op[(size_t)t * ostride] = sq * sq * sig;

        // ---- pipeline bookkeeping ----
        if (t + 14 < TT) issue(t + 14);
        else CP_COMMIT();        // keep group accounting uniform
        CP_WAIT(13);             // stages t+1 (and older) resident
        __syncthreads();

        if (t + 1 < TT) {
            const float* st = ring + ((t + 1) % SDEPTH) * STG_F;
            float4 k0 = *(const float4*)(st + ch8);
            float4 k1 = *(const float4*)(st + ch8 + 4);
            float4 q0 = *(const float4*)(st + 128 + ch8);
            float4 q1 = *(const float4*)(st + 128 + ch8 + 4);
            kc[0]=k0.x; kc[1]=k0.y; kc[2]=k0.z; kc[3]=k0.w;
            kc[4]=k1.x; kc[5]=k1.y; kc[6]=k1.z; kc[7]=k1.w;
            qc[0]=q0.x; qc[1]=q0.y; qc[2]=q0.z; qc[3]=q0.w;
            qc[4]=q1.x; qc[5]=q1.y; qc[6]=q1.z; qc[7]=q1.w;
            vv = st[64 + ch8 + lane];
        }
    }

    if (write_sf) {
        float* sf = out + (size_t)MM * NS + (size_t)c * 64 + lane * 8;
#pragma unroll
        for (int j = 0; j < 8; j++) sf[j] = S[j];
    }
}

// ---------------------------------------------------------------------------
extern "C" void kernel_launch(void* const* d_in, const int* in_sizes, int n_in,
                              void* d_out, int out_size)
{
    (void)in_sizes; (void)n_in;
    const float* x  = (const float*)d_in[0];
    const float* wk = (const float*)d_in[1];
    const float* wv = (const float*)d_in[2];
    const float* wq = (const float*)d_in[3];
    float* out = (float*)d_out;

    convert_x_kernel<<<(MM * DD / 4) / 256, 256>>>(x);
    convert_w_kernel<<<(3 * NS * DD / 4) / 256, 256>>>(wk, wv, wq);

    cudaFuncSetAttribute(gemm_kernel, cudaFuncAttributeMaxDynamicSharedMemorySize, GEMM_SMEM);
    dim3 ggrid(NP / TN, MM / TM);   // 24 x 128
    gemm_kernel<<<ggrid, 256, GEMM_SMEM>>>();

    const long long n_out   = (long long)MM * NS;
    const long long n_state = (long long)BB * NBLK * 64;
    int write_sf = ((long long)out_size >= n_out + n_state) ? 1 : 0;
    scan_kernel<<<128, 64>>>(out, write_sf);
}

// round 6
// speedup vs baseline: 1.5879x; 1.0515x over previous
#include <cuda_runtime.h>
#include <cuda_bf16.h>
#include <math.h>
#include <stdint.h>

// Problem constants
#define TT 2048
#define BB 8
#define DD 1024
#define NS 1024
#define NBLK 128
#define MM (TT*BB)        // 16384 projection rows
#define KP 3072           // K' = 3*D  (bf16x3 split concatenated along K)
#define NP 3072           // N' = 3*N_STATE (k,v,q concatenated along N)

// Scratch (device globals: no cudaMalloc allowed)
__device__ __nv_bfloat16 g_A[(size_t)MM * KP];   // [Ah | Ah | Al]
__device__ __nv_bfloat16 g_B[(size_t)NP * KP];   // rows: Wk,Wv,Wq; cols: [Bh | Bl | Bh]
__device__ float         g_P[(size_t)MM * NP];   // cols 0-1023=k, 1024-2047=v, 2048-3071=q

// ---------------------------------------------------------------------------
// Helpers
// ---------------------------------------------------------------------------
static __device__ __forceinline__ uint32_t smem_u32(const void* p) {
    uint32_t a;
    asm("{ .reg .u64 t; cvta.to.shared.u64 t, %1; cvt.u32.u64 %0, t; }" : "=r"(a) : "l"(p));
    return a;
}
#define SWZ(off) ((off) ^ (((off) >> 3) & 0x70))

#define CP_ASYNC16(saddr, gaddr) \
    asm volatile("cp.async.cg.shared.global [%0], [%1], 16;" :: "r"(saddr), "l"(gaddr))
#define CP_ASYNC4(saddr, gaddr) \
    asm volatile("cp.async.ca.shared.global [%0], [%1], 4;" :: "r"(saddr), "l"(gaddr))
#define CP_COMMIT() asm volatile("cp.async.commit_group;" ::: "memory")
#define CP_WAIT(n)  asm volatile("cp.async.wait_group %0;" :: "n"(n) : "memory")

#define LDSM_X4(r0, r1, r2, r3, addr) \
    asm volatile("ldmatrix.sync.aligned.m8n8.x4.shared.b16 {%0,%1,%2,%3}, [%4];" \
                 : "=r"(r0), "=r"(r1), "=r"(r2), "=r"(r3) : "r"(addr))

static __device__ __forceinline__ void mma16816(float* d, const uint32_t* a,
                                                const uint32_t* b) {
    asm volatile(
        "mma.sync.aligned.m16n8k16.row.col.f32.bf16.bf16.f32 "
        "{%0,%1,%2,%3}, {%4,%5,%6,%7}, {%8,%9}, {%0,%1,%2,%3};"
        : "+f"(d[0]), "+f"(d[1]), "+f"(d[2]), "+f"(d[3])
        : "r"(a[0]), "r"(a[1]), "r"(a[2]), "r"(a[3]), "r"(b[0]), "r"(b[1]));
}

// Fast-math primitives (MUFU)
static __device__ __forceinline__ float f_ex2(float x)  { float r; asm("ex2.approx.f32 %0, %1;"  : "=f"(r) : "f"(x)); return r; }
static __device__ __forceinline__ float f_rcp(float x)  { float r; asm("rcp.approx.f32 %0, %1;"  : "=f"(r) : "f"(x)); return r; }
static __device__ __forceinline__ float f_sqrt(float x) { float r; asm("sqrt.approx.f32 %0, %1;" : "=f"(r) : "f"(x)); return r; }

// dot8 as two independent fma chains (9 ops, ~20cy)
static __device__ __forceinline__ float dot8(const float* a, const float* b) {
    float p = a[0]*b[0]; p = fmaf(a[1],b[1],p); p = fmaf(a[2],b[2],p); p = fmaf(a[3],b[3],p);
    float q = a[4]*b[4]; q = fmaf(a[5],b[5],q); q = fmaf(a[6],b[6],q); q = fmaf(a[7],b[7],q);
    return p + q;
}

// ---------------------------------------------------------------------------
// Conversion: fp32 -> bf16 hi/lo split, concatenated along K
// ---------------------------------------------------------------------------
static __device__ __forceinline__ uint2 pack4(const float* f, bool lo_part) {
    unsigned short h[4];
#pragma unroll
    for (int j = 0; j < 4; j++) {
        __nv_bfloat16 hi = __float2bfloat16(f[j]);
        if (!lo_part) h[j] = __bfloat16_as_ushort(hi);
        else          h[j] = __bfloat16_as_ushort(__float2bfloat16(f[j] - __bfloat162float(hi)));
    }
    uint2 r;
    r.x = (uint32_t)h[0] | ((uint32_t)h[1] << 16);
    r.y = (uint32_t)h[2] | ((uint32_t)h[3] << 16);
    return r;
}

__global__ void __launch_bounds__(256)
convert_x_kernel(const float* __restrict__ X) {
    size_t i = (size_t)blockIdx.x * 256 + threadIdx.x;
    size_t e = i * 4;
    size_t m = e / DD;
    int    c = (int)(e % DD);
    float4 a = *(const float4*)(X + e);
    float f[4] = {a.x, a.y, a.z, a.w};
    uint2 hp = pack4(f, false);
    uint2 lp = pack4(f, true);
    __nv_bfloat16* row = g_A + m * KP;
    *(uint2*)(row + c)        = hp;
    *(uint2*)(row + c + DD)   = hp;
    *(uint2*)(row + c + 2*DD) = lp;
}

__global__ void __launch_bounds__(256)
convert_w_kernel(const float* __restrict__ Wk, const float* __restrict__ Wv,
                 const float* __restrict__ Wq) {
    size_t i = (size_t)blockIdx.x * 256 + threadIdx.x;
    size_t e = i * 4;
    int    w = (int)(e / ((size_t)NS * DD));
    size_t r = e % ((size_t)NS * DD);
    const float* W = (w == 0) ? Wk : ((w == 1) ? Wv : Wq);
    size_t n = r / DD;
    int    c = (int)(r % DD);
    float4 a = *(const float4*)(W + r);
    float f[4] = {a.x, a.y, a.z, a.w};
    uint2 hp = pack4(f, false);
    uint2 lp = pack4(f, true);
    __nv_bfloat16* row = g_B + ((size_t)w * NS + n) * KP;
    *(uint2*)(row + c)        = hp;
    *(uint2*)(row + c + DD)   = lp;
    *(uint2*)(row + c + 2*DD) = hp;
}

// ---------------------------------------------------------------------------
// bf16 GEMM via mma.sync (unchanged from round 5)
// ---------------------------------------------------------------------------
#define TM 128
#define TN 128
#define CK 64
#define NCH (KP / CK)     // 48
#define STAGES 3
#define STG_BYTES (2 * TM * CK * 2)
#define GEMM_SMEM (STAGES * STG_BYTES)

__global__ void __launch_bounds__(256, 2)
gemm_kernel() {
    extern __shared__ char smem[];
    const uint32_t sb  = smem_u32(smem);
    const int tid = threadIdx.x;
    const int wid = tid >> 5;
    const int lid = tid & 31;
    const size_t bm = (size_t)blockIdx.y * TM;
    const size_t bn = (size_t)blockIdx.x * TN;

    const int wm = wid & 1;
    const int wn = wid >> 1;

    const __nv_bfloat16* Abase = g_A + bm * KP;
    const __nv_bfloat16* Bbase = g_B + bn * KP;

    auto issue_stage = [&](int i) {
        const uint32_t abuf = sb + (i % STAGES) * STG_BYTES;
        const uint32_t bbuf = abuf + TM * CK * 2;
        const __nv_bfloat16* As = Abase + i * CK;
        const __nv_bfloat16* Bs = Bbase + i * CK;
#pragma unroll
        for (int u = 0; u < 4; u++) {
            int unit = tid + u * 256;
            int r = unit >> 3, c = unit & 7;
            uint32_t off = SWZ(r * 128 + c * 16);
            CP_ASYNC16(abuf + off, (const char*)(As + (size_t)r * KP + c * 8));
            CP_ASYNC16(bbuf + off, (const char*)(Bs + (size_t)r * KP + c * 8));
        }
        CP_COMMIT();
    };

    issue_stage(0);
    issue_stage(1);

    float acc[4][4][4];
#pragma unroll
    for (int i = 0; i < 4; i++)
#pragma unroll
        for (int j = 0; j < 4; j++)
#pragma unroll
            for (int r = 0; r < 4; r++) acc[i][j][r] = 0.0f;

    const int lrow  = (lid & 7) + ((lid >> 3) & 1) * 8;
    const int chalf = lid >> 4;

    for (int it = 0; it < NCH; it++) {
        CP_WAIT(1);
        __syncthreads();
        if (it + 2 < NCH) issue_stage(it + 2);
        else CP_COMMIT();

        const uint32_t abuf = sb + (it % STAGES) * STG_BYTES;
        const uint32_t bbuf = abuf + TM * CK * 2;

#pragma unroll
        for (int s = 0; s < 4; s++) {
            const int ch = 2 * s + chalf;
            uint32_t a[4][4];
#pragma unroll
            for (int mf = 0; mf < 4; mf++) {
                uint32_t addr = abuf + SWZ((wm * 64 + mf * 16 + lrow) * 128 + ch * 16);
                LDSM_X4(a[mf][0], a[mf][1], a[mf][2], a[mf][3], addr);
            }
            uint32_t b[2][4];
#pragma unroll
            for (int nf2 = 0; nf2 < 2; nf2++) {
                uint32_t addr = bbuf + SWZ((wn * 32 + nf2 * 16 + lrow) * 128 + ch * 16);
                LDSM_X4(b[nf2][0], b[nf2][1], b[nf2][2], b[nf2][3], addr);
            }
#pragma unroll
            for (int mf = 0; mf < 4; mf++) {
#pragma unroll
                for (int nf = 0; nf < 4; nf++) {
                    uint32_t bb_[2] = { b[nf >> 1][(nf & 1)], b[nf >> 1][(nf & 1) + 2] };
                    mma16816(acc[mf][nf], a[mf], bb_);
                }
            }
        }
    }

    const int r0 = lid >> 2;
    const int cp = (lid & 3) * 2;
#pragma unroll
    for (int mf = 0; mf < 4; mf++) {
#pragma unroll
        for (int nf = 0; nf < 4; nf++) {
            float* dst = g_P + (bm + wm * 64 + mf * 16 + r0) * (size_t)NP
                             + bn + wn * 32 + nf * 8 + cp;
            *(float2*)dst = make_float2(acc[mf][nf][0], acc[mf][nf][1]);
            *(float2*)(dst + 8 * NP) = make_float2(acc[mf][nf][2], acc[mf][nf][3]);
        }
    }
}

// ---------------------------------------------------------------------------
// Recurrent delta-rule scan: per-WARP cp.async ring (warp-local data only,
// __syncwarp instead of __syncthreads), software-pipelined so k-normalization
// of step t+1 and the silu/store of step t execute under the tanh latency of
// step t. Ping-pong register sets via 2x-unrolled loop.
// ---------------------------------------------------------------------------
#define SDEPTH 16

__global__ void __launch_bounds__(64)
scan_kernel(float* __restrict__ out, int write_sf)
{
    __shared__ float ring[SDEPTH * 192];   // [stage][warp][k32|v32|q32]

    const int tid  = threadIdx.x;
    const int w    = tid >> 5;      // warp in block
    const int l    = tid & 31;      // lane
    const int lane = tid & 7;       // row within chain
    const int c    = blockIdx.x * 8 + (tid >> 3);   // chain id
    const int b    = blockIdx.x >> 4;               // batch
    const int nb   = c & 127;

    // this warp's 4 chains cover 32 consecutive columns
    const int col0 = (blockIdx.x & 15) * 64 + w * 32;
    const float* src = g_P + (size_t)b * NP + col0;
    const size_t pstep = (size_t)BB * NP;

    const uint32_t rb = smem_u32(ring) + w * 384;   // warp slice (96 floats)
    const float* myslice = ring + w * 96;
    const int ch8 = l & 24;                          // chain-in-warp * 8

    auto issue = [&](int t) {
        const float* s = src + (size_t)t * pstep;
        uint32_t st = rb + (t & (SDEPTH - 1)) * 768;  // 192 floats * 4B
        CP_ASYNC4(st + l * 4,       (const char*)(s + l));
        CP_ASYNC4(st + 128 + l * 4, (const char*)(s + NS + l));
        CP_ASYNC4(st + 256 + l * 4, (const char*)(s + 2 * NS + l));
        CP_COMMIT();
    };

    // load stage regs + normalize k (all off the S critical chain)
    auto load_prep = [&](int t, float* kn, float* qc, float& vv) {
        const float* fs = myslice + (t & (SDEPTH - 1)) * 192;
        float4 k0 = *(const float4*)(fs + ch8);
        float4 k1 = *(const float4*)(fs + ch8 + 4);
        float4 q0 = *(const float4*)(fs + 64 + ch8);
        float4 q1 = *(const float4*)(fs + 64 + ch8 + 4);
        vv = fs[32 + ch8 + lane];
        float kc[8] = {k0.x,k0.y,k0.z,k0.w,k1.x,k1.y,k1.z,k1.w};
        float ss  = dot8(kc, kc);
        float inv = f_rcp(f_sqrt(ss) + 1e-6f);
#pragma unroll
        for (int j = 0; j < 8; j++) kn[j] = kc[j] * inv;
        qc[0]=q0.x; qc[1]=q0.y; qc[2]=q0.z; qc[3]=q0.w;
        qc[4]=q1.x; qc[5]=q1.y; qc[6]=q1.z; qc[7]=q1.w;
    };

    float* op = out + (size_t)b * NS + nb * 8 + lane;
    const int ostride = BB * NS;

    float S[8];
#pragma unroll
    for (int j = 0; j < 8; j++) S[j] = 0.0f;

    // prologue: 14 stages in flight
    for (int s = 0; s < 14; s++) issue(s);
    CP_WAIT(13);
    __syncwarp();

    float knA[8], qcA[8], vvA, knB[8], qcB[8], vvB;
    load_prep(0, knA, qcA, vvA);

    auto step = [&](int t, const float* kn, const float* qc, float vv,
                    float* knN, float* qcN, float& vvN) {
        // keep the pipe fed (independent of S)
        if (t + 14 < TT) issue(t + 14);
        else CP_COMMIT();

        // --- S critical chain ---
        float r = dot8(S, kn);
        float delta = vv - r;
        float u[8];
#pragma unroll
        for (int j = 0; j < 8; j++)
            u[j] = f_ex2(fmaf(delta, kn[j], S[j]) * 2.8853900817779268f);
#pragma unroll
        for (int j = 0; j < 8; j++)
            S[j] = fmaf(-2.0f, f_rcp(u[j] + 1.0f), 1.0f);

        // --- fill tanh latency: advance pipeline + prep t+1 ---
        CP_WAIT(13);
        __syncwarp();
        if (t + 1 < TT) load_prep(t + 1, knN, qcN, vvN);

        // --- output for t (needs new S) ---
        float sq  = dot8(S, qc);
        float sig = f_rcp(1.0f + f_ex2(sq * -1.4426950408889634f));
        op[(size_t)t * ostride] = sq * sq * sig;
    };

    for (int t = 0; t < TT; t += 2) {
        step(t,     knA, qcA, vvA, knB, qcB, vvB);
        step(t + 1, knB, qcB, vvB, knA, qcA, vvA);
    }

    if (write_sf) {
        float* sf = out + (size_t)MM * NS + (size_t)c * 64 + lane * 8;
#pragma unroll
        for (int j = 0; j < 8; j++) sf[j] = S[j];
    }
}

// ---------------------------------------------------------------------------
extern "C" void kernel_launch(void* const* d_in, const int* in_sizes, int n_in,
                              void* d_out, int out_size)
{
    (void)in_sizes; (void)n_in;
    const float* x  = (const float*)d_in[0];
    const float* wk = (const float*)d_in[1];
    const float* wv = (const float*)d_in[2];
    const float* wq = (const float*)d_in[3];
    float* out = (float*)d_out;

    convert_x_kernel<<<(MM * DD / 4) / 256, 256>>>(x);
    convert_w_kernel<<<(3 * NS * DD / 4) / 256, 256>>>(wk, wv, wq);

    cudaFuncSetAttribute(gemm_kernel, cudaFuncAttributeMaxDynamicSharedMemorySize, GEMM_SMEM);
    dim3 ggrid(NP / TN, MM / TM);   // 24 x 128
    gemm_kernel<<<ggrid, 256, GEMM_SMEM>>>();

    const long long n_out   = (long long)MM * NS;
    const long long n_state = (long long)BB * NBLK * 64;
    int write_sf = ((long long)out_size >= n_out + n_state) ? 1 : 0;
    scan_kernel<<<128, 64>>>(out, write_sf);
}